// round 9
// baseline (speedup 1.0000x reference)
#include <cuda_runtime.h>
#include <cstdint>

// PolyConv: CSR build + warp-per-node fp32 iterations.
// Each warp owns one node; lane = feature. Gathers are one coalesced
// 128B line per edge; edge records are loaded coalesced 32-at-a-time.
// Inputs: feat [N*32 f32], src [E i32], dst [E i32], mask [E f32]
// Output: h [N*32 f32]

#define N_NODES 100000
#define N_EDGES 1600000
#define DFEAT   32
#define NF      (N_NODES * DFEAT)

#define SCAN_B  1024
#define N_SBLK  ((N_NODES + SCAN_B - 1) / SCAN_B)   // 98

// ---- scratch (static __device__, no allocation) ----
__device__ int    g_cnt[N_NODES];
__device__ int    g_row[N_NODES + 1];
__device__ int    g_cursor[N_NODES];
__device__ int    g_bsum[N_SBLK];
__device__ float2 g_fac[N_NODES];        // {dinv^2, sqrt(max(deg,1))}
__device__ int2   g_edges[N_EDGES];      // CSR: {src, mask_bits} grouped by dst
__device__ float  g_bufA[NF];            // fp32 scaled state (ping)
__device__ float  g_bufB[NF];            // fp32 scaled state (pong)

// ---------------------------------------------------------------------------
__global__ void k_zero() {
    int i = blockIdx.x * blockDim.x + threadIdx.x;
    if (i < N_NODES) g_cnt[i] = 0;
}

__global__ void k_hist(const int* __restrict__ dst, int E) {
    int e = blockIdx.x * blockDim.x + threadIdx.x;
    if (e < E) atomicAdd(&g_cnt[dst[e]], 1);
}

// scan stage 1: shuffle-based per-block exclusive scan of g_cnt -> g_row.
__global__ void k_scan1() {
    __shared__ int warp_sums[32];
    int t = threadIdx.x;
    int lane = t & 31, warp = t >> 5;
    int gid = blockIdx.x * SCAN_B + t;
    int v = (gid < N_NODES) ? g_cnt[gid] : 0;

    int x = v;
    #pragma unroll
    for (int o = 1; o < 32; o <<= 1) {
        int y = __shfl_up_sync(0xFFFFFFFFu, x, o);
        if (lane >= o) x += y;
    }
    if (lane == 31) warp_sums[warp] = x;
    __syncthreads();
    if (warp == 0) {
        int s = warp_sums[lane];
        #pragma unroll
        for (int o = 1; o < 32; o <<= 1) {
            int y = __shfl_up_sync(0xFFFFFFFFu, s, o);
            if (lane >= o) s += y;
        }
        warp_sums[lane] = s;
    }
    __syncthreads();
    int warp_off = (warp > 0) ? warp_sums[warp - 1] : 0;
    int incl = x + warp_off;
    if (gid < N_NODES) g_row[gid] = incl - v;
    if (t == SCAN_B - 1) g_bsum[blockIdx.x] = incl;
}

// stage 2+3: warp-reduce prior block totals, apply offset, init cursor.
__global__ void k_scan23(int E) {
    __shared__ int s_prefix;
    int t = threadIdx.x;
    if (t < 32) {
        int sum = 0;
        for (int b = t; b < (int)blockIdx.x; b += 32) sum += g_bsum[b];
        #pragma unroll
        for (int o = 16; o; o >>= 1) sum += __shfl_xor_sync(0xFFFFFFFFu, sum, o);
        if (t == 0) s_prefix = sum;
    }
    __syncthreads();
    int prefix = s_prefix;

    int gid = blockIdx.x * SCAN_B + t;
    if (gid < N_NODES) {
        int r = g_row[gid] + prefix;
        g_row[gid] = r;
        g_cursor[gid] = r;
    }
    if (gid == 0) g_row[N_NODES] = E;
}

__global__ void k_scatter(const int* __restrict__ src, const int* __restrict__ dst,
                          const float* __restrict__ mask, int E) {
    int e = blockIdx.x * blockDim.x + threadIdx.x;
    if (e >= E) return;
    int d = dst[e];
    int pos = atomicAdd(&g_cursor[d], 1);
    g_edges[pos] = make_int2(src[e], __float_as_int(mask[e]));
}

// fused fac + init: warp per node. Lanes sum mask over edges (coalesced),
// warp-reduce; lane=feature writes bufA = feat*dinv (coalesced 128B).
__global__ void __launch_bounds__(256)
k_facinit(const float* __restrict__ feat) {
    int n = blockIdx.x * 8 + (threadIdx.x >> 5);
    if (n >= N_NODES) return;
    int lane = threadIdx.x & 31;

    int base = g_row[n];
    int end  = g_row[n + 1];
    float deg = 0.0f;
    for (int j = base + lane; j < end; j += 32)
        deg += __int_as_float(g_edges[j].y);
    #pragma unroll
    for (int o = 16; o; o >>= 1) deg += __shfl_xor_sync(0xFFFFFFFFu, deg, o);

    deg = fmaxf(deg, 1.0f);
    float dinv = rsqrtf(deg);
    if (lane == 0) g_fac[n] = make_float2(dinv * dinv, deg * dinv);  // {dinv^2, sqrt(deg)}

    int i = n * DFEAT + lane;
    g_bufA[i] = feat[i] * dinv;
}

// warp-per-node iteration (all fp32).
// flags: bit0 = first iteration (h = theta_prev*s_old + theta*s_new, pure write)
// sel:   1 -> in=bufA out=bufB, 0 -> in=bufB out=bufA
__global__ void __launch_bounds__(256)
k_iter(float* __restrict__ h, float theta, float theta_prev, int flags, int sel) {
    const float* __restrict__ bin  = sel ? g_bufA : g_bufB;
    float* __restrict__       bout = sel ? g_bufB : g_bufA;

    int n = blockIdx.x * 8 + (threadIdx.x >> 5);
    if (n >= N_NODES) return;
    int lane = threadIdx.x & 31;

    int base = g_row[n];
    int end  = g_row[n + 1];

    float acc = 0.0f;
    for (int j0 = base; j0 < end; j0 += 32) {
        int jj = j0 + lane;
        int2 ed = (jj < end) ? g_edges[jj] : make_int2(0, 0);
        int cnt = min(32, end - j0);
        // even k and odd k independent; unroll for MLP
        #pragma unroll 4
        for (int k = 0; k < cnt; ++k) {
            int   sk = __shfl_sync(0xFFFFFFFFu, ed.x, k);
            float mk = __int_as_float(__shfl_sync(0xFFFFFFFFu, ed.y, k));
            acc += bin[sk * DFEAT + lane] * mk;   // one coalesced 128B line
        }
    }

    float2 fac = g_fac[n];
    float dinv2 = fac.x, rsq = fac.y;

    int i = n * DFEAT + lane;
    float s_old = bin[i];
    float s_new = s_old - acc * dinv2;
    bout[i] = s_new;

    float tr = theta * rsq;
    if (flags & 1) {
        h[i] = theta_prev * rsq * s_old + tr * s_new;
    } else {
        h[i] += tr * s_new;
    }
}

extern "C" void kernel_launch(void* const* d_in, const int* in_sizes, int n_in,
                              void* d_out, int out_size) {
    const float* feat = (const float*)d_in[0];
    const int*   src  = (const int*)d_in[1];
    const int*   dst  = (const int*)d_in[2];
    const float* mask = (const float*)d_in[3];
    float* out = (float*)d_out;

    const int E = in_sizes[1];
    const int TB = 256;

    // --- CSR build ---
    k_zero<<<(N_NODES + TB - 1) / TB, TB>>>();
    k_hist<<<(E + TB - 1) / TB, TB>>>(dst, E);
    k_scan1<<<N_SBLK, SCAN_B>>>();
    k_scan23<<<N_SBLK, SCAN_B>>>(E);
    k_scatter<<<(E + TB - 1) / TB, TB>>>(src, dst, mask, E);

    // --- factors + init (fused), warp per node ---
    int wnode_blocks = (N_NODES + 7) / 8;
    k_facinit<<<wnode_blocks, TB>>>(feat);

    // --- 4 iterations ---  theta = {0.2, -0.4, 0.3, -0.15, 0.05}
    k_iter<<<wnode_blocks, TB>>>(out, -0.4f, 0.2f, 1, 1);  // A->B, h pure write
    k_iter<<<wnode_blocks, TB>>>(out, 0.3f,  0.0f, 0, 0);  // B->A
    k_iter<<<wnode_blocks, TB>>>(out, -0.15f,0.0f, 0, 1);  // A->B
    k_iter<<<wnode_blocks, TB>>>(out, 0.05f, 0.0f, 0, 0);  // B->A
}

// round 10
// speedup vs baseline: 1.1380x; 1.1380x over previous
#include <cuda_runtime.h>
#include <cuda_fp16.h>
#include <cstdint>

// PolyConv: CSR build + warp-per-node iterations with SMEM-staged edge records.
// Warp owns a node; lane = feature. Gather = one coalesced line per edge.
// State fp32 ping-pong; gather fp32 (iter1) then fp16 mirror (iters 2-4).
// Inputs: feat [N*32 f32], src [E i32], dst [E i32], mask [E f32]
// Output: h [N*32 f32]

#define N_NODES 100000
#define N_EDGES 1600000
#define DFEAT   32
#define NF      (N_NODES * DFEAT)

#define SCAN_B  1024
#define N_SBLK  ((N_NODES + SCAN_B - 1) / SCAN_B)   // 98

// ---- scratch (static __device__, no allocation) ----
__device__ int    g_cnt[N_NODES];
__device__ int    g_row[N_NODES + 1];
__device__ int    g_cursor[N_NODES];
__device__ int    g_bsum[N_SBLK];
__device__ float2 g_fac[N_NODES];        // {dinv^2, sqrt(max(deg,1))}
__device__ int2   g_edges[N_EDGES];      // CSR: {src, mask_bits} grouped by dst
__device__ float  g_bufA[NF];            // fp32 state (ping)
__device__ float  g_bufB[NF];            // fp32 state (pong)
__device__ __half g_h16A[NF];            // fp16 gather mirror (ping)
__device__ __half g_h16B[NF];            // fp16 gather mirror (pong)

// ---------------------------------------------------------------------------
__global__ void k_zero() {
    int i = blockIdx.x * blockDim.x + threadIdx.x;
    if (i < N_NODES) g_cnt[i] = 0;
}

__global__ void k_hist(const int* __restrict__ dst, int E) {
    int e = blockIdx.x * blockDim.x + threadIdx.x;
    if (e < E) atomicAdd(&g_cnt[dst[e]], 1);
}

// scan stage 1: shuffle-based per-block exclusive scan of g_cnt -> g_row.
__global__ void k_scan1() {
    __shared__ int warp_sums[32];
    int t = threadIdx.x;
    int lane = t & 31, warp = t >> 5;
    int gid = blockIdx.x * SCAN_B + t;
    int v = (gid < N_NODES) ? g_cnt[gid] : 0;

    int x = v;
    #pragma unroll
    for (int o = 1; o < 32; o <<= 1) {
        int y = __shfl_up_sync(0xFFFFFFFFu, x, o);
        if (lane >= o) x += y;
    }
    if (lane == 31) warp_sums[warp] = x;
    __syncthreads();
    if (warp == 0) {
        int s = warp_sums[lane];
        #pragma unroll
        for (int o = 1; o < 32; o <<= 1) {
            int y = __shfl_up_sync(0xFFFFFFFFu, s, o);
            if (lane >= o) s += y;
        }
        warp_sums[lane] = s;
    }
    __syncthreads();
    int warp_off = (warp > 0) ? warp_sums[warp - 1] : 0;
    int incl = x + warp_off;
    if (gid < N_NODES) g_row[gid] = incl - v;
    if (t == SCAN_B - 1) g_bsum[blockIdx.x] = incl;
}

// stage 2+3: warp-reduce prior block totals, apply offset, init cursor.
__global__ void k_scan23(int E) {
    __shared__ int s_prefix;
    int t = threadIdx.x;
    if (t < 32) {
        int sum = 0;
        for (int b = t; b < (int)blockIdx.x; b += 32) sum += g_bsum[b];
        #pragma unroll
        for (int o = 16; o; o >>= 1) sum += __shfl_xor_sync(0xFFFFFFFFu, sum, o);
        if (t == 0) s_prefix = sum;
    }
    __syncthreads();
    int prefix = s_prefix;

    int gid = blockIdx.x * SCAN_B + t;
    if (gid < N_NODES) {
        int r = g_row[gid] + prefix;
        g_row[gid] = r;
        g_cursor[gid] = r;
    }
    if (gid == 0) g_row[N_NODES] = E;
}

__global__ void k_scatter(const int* __restrict__ src, const int* __restrict__ dst,
                          const float* __restrict__ mask, int E) {
    int e = blockIdx.x * blockDim.x + threadIdx.x;
    if (e >= E) return;
    int d = dst[e];
    int pos = atomicAdd(&g_cursor[d], 1);
    g_edges[pos] = make_int2(src[e], __float_as_int(mask[e]));
}

// fused fac + init: warp per node. Coalesced mask sum + warp reduce; write
// bufA = feat*dinv (coalesced 128B per node row).
__global__ void __launch_bounds__(256)
k_facinit(const float* __restrict__ feat) {
    int n = blockIdx.x * 8 + (threadIdx.x >> 5);
    if (n >= N_NODES) return;
    int lane = threadIdx.x & 31;

    int base = g_row[n];
    int end  = g_row[n + 1];
    float deg = 0.0f;
    for (int j = base + lane; j < end; j += 32)
        deg += __int_as_float(g_edges[j].y);
    #pragma unroll
    for (int o = 16; o; o >>= 1) deg += __shfl_xor_sync(0xFFFFFFFFu, deg, o);

    deg = fmaxf(deg, 1.0f);
    float dinv = rsqrtf(deg);
    if (lane == 0) g_fac[n] = make_float2(dinv * dinv, deg * dinv);  // {dinv^2, sqrt(deg)}

    int i = n * DFEAT + lane;
    g_bufA[i] = feat[i] * dinv;
}

// iteration 1 (fp32 gather): warp per node, SMEM-staged edge records.
// in: bufA (fp32). out: bufB (fp32 state) + h16A (fp16 mirror) + h (pure write).
__global__ void __launch_bounds__(256)
k_iter1(float* __restrict__ h, float theta0, float theta1) {
    __shared__ int2 sh_ed[8][32];
    int warp = threadIdx.x >> 5;
    int lane = threadIdx.x & 31;
    int n = blockIdx.x * 8 + warp;
    if (n >= N_NODES) return;

    int base = g_row[n];
    int end  = g_row[n + 1];

    float acc = 0.0f;
    for (int j0 = base; j0 < end; j0 += 32) {
        int jj = j0 + lane;
        if (jj < end) sh_ed[warp][lane] = g_edges[jj];
        __syncwarp();
        int cnt = min(32, end - j0);
        #pragma unroll 4
        for (int k = 0; k < cnt; ++k) {
            int2 ed = sh_ed[warp][k];                       // LDS broadcast
            acc += g_bufA[ed.x * DFEAT + lane] * __int_as_float(ed.y);
        }
        __syncwarp();
    }

    float2 fac = g_fac[n];
    float dinv2 = fac.x, rsq = fac.y;

    int i = n * DFEAT + lane;
    float s_old = g_bufA[i];
    float s_new = s_old - acc * dinv2;
    g_bufB[i] = s_new;
    g_h16A[i] = __float2half(s_new);

    h[i] = theta0 * rsq * s_old + theta1 * rsq * s_new;
}

// iterations 2-4 (fp16 gather): warp per node, SMEM-staged edge records.
// sel16: 1 -> gather h16A, write h16B; 0 -> gather h16B, write h16A.
// selS:  1 -> state in bufB out bufA; 0 -> state in bufA out bufB.
// write_next: write fp16 mirror for next iteration.
__global__ void __launch_bounds__(256)
k_iter(float* __restrict__ h, float theta, int write_next, int sel16, int selS) {
    const __half* __restrict__ gin  = sel16 ? g_h16A : g_h16B;
    __half* __restrict__       gout = sel16 ? g_h16B : g_h16A;
    const float* __restrict__  sin_ = selS ? g_bufB : g_bufA;
    float* __restrict__        sout = selS ? g_bufA : g_bufB;

    __shared__ int2 sh_ed[8][32];
    int warp = threadIdx.x >> 5;
    int lane = threadIdx.x & 31;
    int n = blockIdx.x * 8 + warp;
    if (n >= N_NODES) return;

    int base = g_row[n];
    int end  = g_row[n + 1];

    float acc = 0.0f;
    for (int j0 = base; j0 < end; j0 += 32) {
        int jj = j0 + lane;
        if (jj < end) sh_ed[warp][lane] = g_edges[jj];
        __syncwarp();
        int cnt = min(32, end - j0);
        #pragma unroll 4
        for (int k = 0; k < cnt; ++k) {
            int2 ed = sh_ed[warp][k];                       // LDS broadcast
            float v = __half2float(gin[ed.x * DFEAT + lane]); // coalesced 64B
            acc += v * __int_as_float(ed.y);
        }
        __syncwarp();
    }

    float2 fac = g_fac[n];
    float dinv2 = fac.x, rsq = fac.y;

    int i = n * DFEAT + lane;
    float s_old = sin_[i];
    float s_new = s_old - acc * dinv2;
    sout[i] = s_new;

    h[i] += theta * rsq * s_new;

    if (write_next) gout[i] = __float2half(s_new);
}

extern "C" void kernel_launch(void* const* d_in, const int* in_sizes, int n_in,
                              void* d_out, int out_size) {
    const float* feat = (const float*)d_in[0];
    const int*   src  = (const int*)d_in[1];
    const int*   dst  = (const int*)d_in[2];
    const float* mask = (const float*)d_in[3];
    float* out = (float*)d_out;

    const int E = in_sizes[1];
    const int TB = 256;

    // --- CSR build ---
    k_zero<<<(N_NODES + TB - 1) / TB, TB>>>();
    k_hist<<<(E + TB - 1) / TB, TB>>>(dst, E);
    k_scan1<<<N_SBLK, SCAN_B>>>();
    k_scan23<<<N_SBLK, SCAN_B>>>(E);
    k_scatter<<<(E + TB - 1) / TB, TB>>>(src, dst, mask, E);

    // --- factors + init (fused), warp per node ---
    int wnode_blocks = (N_NODES + 7) / 8;
    k_facinit<<<wnode_blocks, TB>>>(feat);

    // --- 4 iterations ---  theta = {0.2, -0.4, 0.3, -0.15, 0.05}
    // iter1: bufA -> bufB (+h16A), h = 0.2*T0 + (-0.4)*T1
    k_iter1<<<wnode_blocks, TB>>>(out, 0.2f, -0.4f);
    // iter2: gather h16A, state bufB -> bufA, write h16B
    k_iter<<<wnode_blocks, TB>>>(out, 0.3f,   1, 1, 1);
    // iter3: gather h16B, state bufA -> bufB, write h16A
    k_iter<<<wnode_blocks, TB>>>(out, -0.15f, 1, 0, 0);
    // iter4: gather h16A, state bufB -> bufA, no mirror write
    k_iter<<<wnode_blocks, TB>>>(out, 0.05f,  0, 1, 1);
}

// round 11
// speedup vs baseline: 1.4017x; 1.2317x over previous
#include <cuda_runtime.h>
#include <cuda_fp16.h>
#include <cstdint>

// PolyConv: CSR build + atomic-free fused iterations, 4-lane node groups
// (8 independent edge loops per warp = high MLP), dual-chain edge pipelining.
// State fp32 in-place; gather fp32 (iter1) then fp16 ping-pong (iters 2-4).
// Inputs: feat [N*32 f32], src [E i32], dst [E i32], mask [E f32]
// Output: h [N*32 f32]

#define N_NODES 100000
#define N_EDGES 1600000
#define DFEAT   32
#define DV4     (DFEAT / 4)        // 8 float4 per node row
#define NV4     (N_NODES * DV4)
#define NH4     (N_NODES * 4)      // 4 uint4 (8 halves) per node row

#define SCAN_B  1024
#define N_SBLK  ((N_NODES + SCAN_B - 1) / SCAN_B)   // 98

// ---- scratch (static __device__, no allocation) ----
__device__ int    g_cnt[N_NODES];
__device__ int    g_row[N_NODES + 1];
__device__ int    g_cursor[N_NODES];
__device__ int    g_bsum[N_SBLK];
__device__ float2 g_fac[N_NODES];        // {dinv^2, sqrt(max(deg,1))}
__device__ int2   g_edges[N_EDGES];      // CSR: {src, mask_bits} grouped by dst
__device__ float4 g_src32[NV4];          // fp32 gather source for iter1 (T0 scaled)
__device__ float4 g_scaled[NV4];         // fp32 state, in-place
__device__ uint4  g_halfA[NH4];          // fp16 gather copy (ping)
__device__ uint4  g_halfB[NH4];          // fp16 gather copy (pong)

static __device__ __forceinline__ unsigned h2u(__half2 h) {
    return *reinterpret_cast<unsigned*>(&h);
}

// ---------------------------------------------------------------------------
__global__ void k_zero() {
    int i = blockIdx.x * blockDim.x + threadIdx.x;
    if (i < N_NODES) g_cnt[i] = 0;
}

__global__ void k_hist(const int* __restrict__ dst, int E) {
    int e = blockIdx.x * blockDim.x + threadIdx.x;
    if (e < E) atomicAdd(&g_cnt[dst[e]], 1);
}

// scan stage 1: shuffle-based per-block exclusive scan of g_cnt -> g_row.
__global__ void k_scan1() {
    __shared__ int warp_sums[32];
    int t = threadIdx.x;
    int lane = t & 31, warp = t >> 5;
    int gid = blockIdx.x * SCAN_B + t;
    int v = (gid < N_NODES) ? g_cnt[gid] : 0;

    int x = v;
    #pragma unroll
    for (int o = 1; o < 32; o <<= 1) {
        int y = __shfl_up_sync(0xFFFFFFFFu, x, o);
        if (lane >= o) x += y;
    }
    if (lane == 31) warp_sums[warp] = x;
    __syncthreads();
    if (warp == 0) {
        int s = warp_sums[lane];
        #pragma unroll
        for (int o = 1; o < 32; o <<= 1) {
            int y = __shfl_up_sync(0xFFFFFFFFu, s, o);
            if (lane >= o) s += y;
        }
        warp_sums[lane] = s;
    }
    __syncthreads();
    int warp_off = (warp > 0) ? warp_sums[warp - 1] : 0;
    int incl = x + warp_off;
    if (gid < N_NODES) g_row[gid] = incl - v;
    if (t == SCAN_B - 1) g_bsum[blockIdx.x] = incl;
}

// stage 2+3: 256-thread blocks; warp 0 reduces the preceding 1024-block totals
// (each lane <=4 loads), then all threads apply offsets + init cursor.
__global__ void k_scan23(int E) {
    __shared__ int s_prefix;
    int t = threadIdx.x;
    int nblk = blockIdx.x >> 2;           // index of this 256-range's 1024-block
    if (t < 32) {
        int sum = 0;
        for (int b = t; b < nblk; b += 32) sum += g_bsum[b];
        #pragma unroll
        for (int o = 16; o; o >>= 1) sum += __shfl_xor_sync(0xFFFFFFFFu, sum, o);
        if (t == 0) s_prefix = sum;
    }
    __syncthreads();
    int prefix = s_prefix;

    int gid = blockIdx.x * 256 + t;
    if (gid < N_NODES) {
        int r = g_row[gid] + prefix;
        g_row[gid] = r;
        g_cursor[gid] = r;
    }
    if (gid == 0) g_row[N_NODES] = E;
}

__global__ void k_scatter(const int* __restrict__ src, const int* __restrict__ dst,
                          const float* __restrict__ mask, int E) {
    int e = blockIdx.x * blockDim.x + threadIdx.x;
    if (e >= E) return;
    int d = dst[e];
    int pos = atomicAdd(&g_cursor[d], 1);
    g_edges[pos] = make_int2(src[e], __float_as_int(mask[e]));
}

// fused fac + init: 4 lanes per node; shuffle-reduce mask sum, write factors
// and src32 = feat*dinv.
__global__ void __launch_bounds__(256)
k_facinit(const float4* __restrict__ feat4) {
    int t = threadIdx.x;
    int n = blockIdx.x * 64 + (t >> 2);
    if (n >= N_NODES) return;
    int c = t & 3;

    int base = g_row[n];
    int end  = g_row[n + 1];
    float deg = 0.0f;
    for (int j = base + c; j < end; j += 4)
        deg += __int_as_float(g_edges[j].y);
    deg += __shfl_xor_sync(0xFFFFFFFFu, deg, 1);
    deg += __shfl_xor_sync(0xFFFFFFFFu, deg, 2);

    deg = fmaxf(deg, 1.0f);
    float dinv = rsqrtf(deg);
    if (c == 0) g_fac[n] = make_float2(dinv * dinv, deg * dinv); // {dinv^2, sqrt(deg)}

    int i0 = n * DV4 + c * 2;
    float4 f0 = feat4[i0], f1 = feat4[i0 + 1];
    float4 s0, s1;
    s0.x = f0.x * dinv; s0.y = f0.y * dinv; s0.z = f0.z * dinv; s0.w = f0.w * dinv;
    s1.x = f1.x * dinv; s1.y = f1.y * dinv; s1.z = f1.z * dinv; s1.w = f1.w * dinv;
    g_src32[i0] = s0;
    g_src32[i0 + 1] = s1;
}

// iteration 1: fp32 gather, dual-chain pipelining.
__global__ void __launch_bounds__(256)
k_iter1(float4* __restrict__ h4, float theta0, float theta1) {
    int t = threadIdx.x;
    int n = blockIdx.x * 64 + (t >> 2);
    if (n >= N_NODES) return;
    int c = t & 3;

    int base = g_row[n];
    int end  = g_row[n + 1];

    // hoisted node state (overlaps with gather chain)
    float2 fac = g_fac[n];
    int i0 = n * DV4 + c * 2;
    float4 o0 = __ldg(&g_src32[i0]), o1 = __ldg(&g_src32[i0 + 1]);

    float a0=0.f,a1=0.f,a2=0.f,a3=0.f,a4=0.f,a5=0.f,a6=0.f,a7=0.f;   // chain A
    float b0=0.f,b1=0.f,b2=0.f,b3=0.f,b4=0.f,b5=0.f,b6=0.f,b7=0.f;   // chain B

    int j = base;
    #pragma unroll 2
    for (; j + 2 <= end; j += 2) {
        int2 e0 = g_edges[j];
        int2 e1 = g_edges[j + 1];
        const float4* p0 = &g_src32[e0.x * DV4 + c * 2];
        const float4* p1 = &g_src32[e1.x * DV4 + c * 2];
        float4 u0 = __ldg(p0), u1 = __ldg(p0 + 1);
        float4 w0 = __ldg(p1), w1 = __ldg(p1 + 1);
        float m0 = __int_as_float(e0.y), m1 = __int_as_float(e1.y);
        a0 += u0.x * m0; a1 += u0.y * m0; a2 += u0.z * m0; a3 += u0.w * m0;
        a4 += u1.x * m0; a5 += u1.y * m0; a6 += u1.z * m0; a7 += u1.w * m0;
        b0 += w0.x * m1; b1 += w0.y * m1; b2 += w0.z * m1; b3 += w0.w * m1;
        b4 += w1.x * m1; b5 += w1.y * m1; b6 += w1.z * m1; b7 += w1.w * m1;
    }
    if (j < end) {
        int2 e0 = g_edges[j];
        const float4* p0 = &g_src32[e0.x * DV4 + c * 2];
        float4 u0 = __ldg(p0), u1 = __ldg(p0 + 1);
        float m0 = __int_as_float(e0.y);
        a0 += u0.x * m0; a1 += u0.y * m0; a2 += u0.z * m0; a3 += u0.w * m0;
        a4 += u1.x * m0; a5 += u1.y * m0; a6 += u1.z * m0; a7 += u1.w * m0;
    }
    a0 += b0; a1 += b1; a2 += b2; a3 += b3;
    a4 += b4; a5 += b5; a6 += b6; a7 += b7;

    float dinv2 = fac.x, rsq = fac.y;
    float4 s0, s1;
    s0.x = o0.x - a0 * dinv2; s0.y = o0.y - a1 * dinv2;
    s0.z = o0.z - a2 * dinv2; s0.w = o0.w - a3 * dinv2;
    s1.x = o1.x - a4 * dinv2; s1.y = o1.y - a5 * dinv2;
    s1.z = o1.z - a6 * dinv2; s1.w = o1.w - a7 * dinv2;
    g_scaled[i0] = s0;
    g_scaled[i0 + 1] = s1;

    float tpr = theta0 * rsq, tr = theta1 * rsq;
    float4 h0, h1;
    h0.x = tpr * o0.x + tr * s0.x; h0.y = tpr * o0.y + tr * s0.y;
    h0.z = tpr * o0.z + tr * s0.z; h0.w = tpr * o0.w + tr * s0.w;
    h1.x = tpr * o1.x + tr * s1.x; h1.y = tpr * o1.y + tr * s1.y;
    h1.z = tpr * o1.z + tr * s1.z; h1.w = tpr * o1.w + tr * s1.w;
    h4[i0] = h0;
    h4[i0 + 1] = h1;

    uint4 hp;
    hp.x = h2u(__floats2half2_rn(s0.x, s0.y));
    hp.y = h2u(__floats2half2_rn(s0.z, s0.w));
    hp.z = h2u(__floats2half2_rn(s1.x, s1.y));
    hp.w = h2u(__floats2half2_rn(s1.z, s1.w));
    g_halfB[n * 4 + c] = hp;
}

// iterations 2-4: fp16 gather, dual-chain pipelining.
// sel: 1 -> in=halfA out=halfB, 0 -> in=halfB out=halfA.
__global__ void __launch_bounds__(256)
k_iter(float4* __restrict__ h4, float theta, int write_next, int sel) {
    const uint4* __restrict__ gin  = sel ? g_halfA : g_halfB;
    uint4* __restrict__       gout = sel ? g_halfB : g_halfA;

    int t = threadIdx.x;
    int n = blockIdx.x * 64 + (t >> 2);
    if (n >= N_NODES) return;
    int c = t & 3;

    int base = g_row[n];
    int end  = g_row[n + 1];

    // hoisted node state
    float2 fac = g_fac[n];
    int i0 = n * DV4 + c * 2;
    float4 s0 = g_scaled[i0], s1 = g_scaled[i0 + 1];

    float a0=0.f,a1=0.f,a2=0.f,a3=0.f,a4=0.f,a5=0.f,a6=0.f,a7=0.f;
    float b0=0.f,b1=0.f,b2=0.f,b3=0.f,b4=0.f,b5=0.f,b6=0.f,b7=0.f;

    int j = base;
    #pragma unroll 2
    for (; j + 2 <= end; j += 2) {
        int2 e0 = g_edges[j];
        int2 e1 = g_edges[j + 1];
        uint4 v0 = __ldg(&gin[e0.x * 4 + c]);
        uint4 v1 = __ldg(&gin[e1.x * 4 + c]);
        float m0 = __int_as_float(e0.y), m1 = __int_as_float(e1.y);
        float2 f;
        f = __half22float2(*reinterpret_cast<__half2*>(&v0.x)); a0 += f.x*m0; a1 += f.y*m0;
        f = __half22float2(*reinterpret_cast<__half2*>(&v0.y)); a2 += f.x*m0; a3 += f.y*m0;
        f = __half22float2(*reinterpret_cast<__half2*>(&v0.z)); a4 += f.x*m0; a5 += f.y*m0;
        f = __half22float2(*reinterpret_cast<__half2*>(&v0.w)); a6 += f.x*m0; a7 += f.y*m0;
        f = __half22float2(*reinterpret_cast<__half2*>(&v1.x)); b0 += f.x*m1; b1 += f.y*m1;
        f = __half22float2(*reinterpret_cast<__half2*>(&v1.y)); b2 += f.x*m1; b3 += f.y*m1;
        f = __half22float2(*reinterpret_cast<__half2*>(&v1.z)); b4 += f.x*m1; b5 += f.y*m1;
        f = __half22float2(*reinterpret_cast<__half2*>(&v1.w)); b6 += f.x*m1; b7 += f.y*m1;
    }
    if (j < end) {
        int2 e0 = g_edges[j];
        uint4 v0 = __ldg(&gin[e0.x * 4 + c]);
        float m0 = __int_as_float(e0.y);
        float2 f;
        f = __half22float2(*reinterpret_cast<__half2*>(&v0.x)); a0 += f.x*m0; a1 += f.y*m0;
        f = __half22float2(*reinterpret_cast<__half2*>(&v0.y)); a2 += f.x*m0; a3 += f.y*m0;
        f = __half22float2(*reinterpret_cast<__half2*>(&v0.z)); a4 += f.x*m0; a5 += f.y*m0;
        f = __half22float2(*reinterpret_cast<__half2*>(&v0.w)); a6 += f.x*m0; a7 += f.y*m0;
    }
    a0 += b0; a1 += b1; a2 += b2; a3 += b3;
    a4 += b4; a5 += b5; a6 += b6; a7 += b7;

    float dinv2 = fac.x, rsq = fac.y;
    s0.x -= a0 * dinv2; s0.y -= a1 * dinv2; s0.z -= a2 * dinv2; s0.w -= a3 * dinv2;
    s1.x -= a4 * dinv2; s1.y -= a5 * dinv2; s1.z -= a6 * dinv2; s1.w -= a7 * dinv2;
    g_scaled[i0] = s0;
    g_scaled[i0 + 1] = s1;

    float tr = theta * rsq;
    float4 h0 = h4[i0], h1 = h4[i0 + 1];
    h0.x += tr * s0.x; h0.y += tr * s0.y; h0.z += tr * s0.z; h0.w += tr * s0.w;
    h1.x += tr * s1.x; h1.y += tr * s1.y; h1.z += tr * s1.z; h1.w += tr * s1.w;
    h4[i0] = h0;
    h4[i0 + 1] = h1;

    if (write_next) {
        uint4 hp;
        hp.x = h2u(__floats2half2_rn(s0.x, s0.y));
        hp.y = h2u(__floats2half2_rn(s0.z, s0.w));
        hp.z = h2u(__floats2half2_rn(s1.x, s1.y));
        hp.w = h2u(__floats2half2_rn(s1.z, s1.w));
        gout[n * 4 + c] = hp;
    }
}

extern "C" void kernel_launch(void* const* d_in, const int* in_sizes, int n_in,
                              void* d_out, int out_size) {
    const float* feat = (const float*)d_in[0];
    const int*   src  = (const int*)d_in[1];
    const int*   dst  = (const int*)d_in[2];
    const float* mask = (const float*)d_in[3];
    float* out = (float*)d_out;

    const int E = in_sizes[1];
    const int TB = 256;

    // --- CSR build ---
    k_zero<<<(N_NODES + TB - 1) / TB, TB>>>();
    k_hist<<<(E + TB - 1) / TB, TB>>>(dst, E);
    k_scan1<<<N_SBLK, SCAN_B>>>();
    k_scan23<<<(N_NODES + 255) / 256, 256>>>(E);
    k_scatter<<<(E + TB - 1) / TB, TB>>>(src, dst, mask, E);

    // --- factors + init (fused) ---
    int node4_blocks = (N_NODES + 63) / 64;
    k_facinit<<<node4_blocks, TB>>>((const float4*)feat);

    // --- 4 fused iterations ---  theta = {0.2, -0.4, 0.3, -0.15, 0.05}
    k_iter1<<<node4_blocks, TB>>>((float4*)out, 0.2f, -0.4f);
    k_iter<<<node4_blocks, TB>>>((float4*)out, 0.3f,   1, 0);  // reads B, writes A
    k_iter<<<node4_blocks, TB>>>((float4*)out, -0.15f, 1, 1);  // reads A, writes B
    k_iter<<<node4_blocks, TB>>>((float4*)out, 0.05f,  0, 0);  // reads B
}